// round 2
// baseline (speedup 1.0000x reference)
#include <cuda_runtime.h>

#define NUM_C   64
#define FD      128
#define FD4     32          // float4 per row
#define BLK     128
#define GRID    148
#define DPTH    16          // software pipeline depth
#define N_PAIRS 2016        // 64*63/2
#define SMEM_BYTES (4*NUM_C*FD4*(int)sizeof(float4) + 64*(int)sizeof(int))  // 128KB + 256B

__device__ float        g_sums[NUM_C * FD];
__device__ int          g_counts[NUM_C];
__device__ float        g_sumsq;
__device__ unsigned int g_ticket;

__global__ void __launch_bounds__(BLK, 1)
fused_k(const float* __restrict__ feat, const int* __restrict__ tgt, int B,
        float* __restrict__ out)
{
    extern __shared__ float4 sm4[];                 // 4 replicas of [64][32] float4
    int* scnt = (int*)(sm4 + 4 * NUM_C * FD4);      // 64 counters

    __shared__ float s_red[4];
    __shared__ float s_hred[4];
    __shared__ int   s_last;

    const int tid = threadIdx.x;
    const int w   = tid >> 5;
    const int l   = tid & 31;
    float4* accw = sm4 + w * (NUM_C * FD4);         // warp-private replica

    // zero replicas + counters
    for (int i = tid; i < 4 * NUM_C * FD4; i += BLK) sm4[i] = make_float4(0.f, 0.f, 0.f, 0.f);
    if (tid < NUM_C) scnt[tid] = 0;
    __syncthreads();

    // block row range
    const int per = (B + GRID - 1) / GRID;
    const int r0  = blockIdx.x * per;
    const int r1  = min(r0 + per, B);
    const int n   = max(r1 - r0, 0);

    // per-block target histogram (kept OUT of the accumulate chain)
    for (int i = tid; i < n; i += BLK) atomicAdd(&scnt[tgt[r0 + i]], 1);

    // ---- main accumulation: warp w handles local rows w, w+4, w+8, ... ----
    const int m = (n > w) ? ((n - w + 3) >> 2) : 0;             // rows for this warp
    const float4* rowp = (const float4*)feat + (size_t)(r0 + w) * FD4 + l;
    const int*    tp   = tgt + r0 + w;

    float4 vr[DPTH];
    int    cr[DPTH];
    float  sq = 0.f;

#pragma unroll
    for (int k = 0; k < DPTH; k++) {
        if (k < m) { vr[k] = rowp[(size_t)k * (4 * FD4)]; cr[k] = tp[k * 4]; }
    }

    const int ngrp = (m + DPTH - 1) / DPTH;
    for (int g = 0; g < ngrp; g++) {
        const int tb = g * DPTH;
#pragma unroll
        for (int u = 0; u < DPTH; u++) {
            const int t = tb + u;
            if (t < m) {
                float4 v = vr[u];
                int    c = cr[u];
                const int tn = t + DPTH;
                if (tn < m) {                       // keep loads DPTH ahead of the chain
                    vr[u] = rowp[(size_t)tn * (4 * FD4)];
                    cr[u] = tp[tn * 4];
                }
                float4* ap = accw + c * FD4 + l;    // warp-private: race-free
                float4 a = *ap;
                a.x += v.x; a.y += v.y; a.z += v.z; a.w += v.w;
                *ap = a;
                sq = fmaf(v.x, v.x, fmaf(v.y, v.y, fmaf(v.z, v.z, fmaf(v.w, v.w, sq))));
            }
        }
    }
    __syncthreads();

    // ---- flush block partials ----
    const float* af = (const float*)sm4;
    for (int i = tid; i < NUM_C * FD; i += BLK) {
        float s = af[i] + af[i + 8192] + af[i + 16384] + af[i + 24576];
        atomicAdd(&g_sums[i], s);
    }
    if (tid < NUM_C) atomicAdd(&g_counts[tid], scnt[tid]);
#pragma unroll
    for (int o = 16; o > 0; o >>= 1) sq += __shfl_down_sync(0xffffffffu, sq, o);
    if (l == 0) atomicAdd(&g_sumsq, sq);

    __threadfence();
    __syncthreads();
    if (tid == 0) {
        unsigned int tk = atomicAdd(&g_ticket, 1u);
        s_last = (tk == gridDim.x - 1);
    }
    __syncthreads();
    if (!s_last) return;

    // ================= last block: epilogue =================
    __threadfence();

    // centers -> smem; ipart = sum_i S_i * cent_i = sum_c cnt_c * ||cent_c||^2
    float* cent = (float*)sm4;                      // [64][128] floats (8KB)
    float ipart = 0.f;
    for (int i = tid; i < NUM_C * FD; i += BLK) {
        const int c = i >> 7;
        float cnt = fmaxf((float)g_counts[c], 1.0f);
        float s   = g_sums[i];
        float ce  = s / cnt;
        cent[i]   = ce;
        ipart    += s * ce;
        g_sums[i] = 0.f;                            // reset for next replay
    }
    float ssq = 0.f;
    __syncthreads();
    if (tid < NUM_C) g_counts[tid] = 0;
    if (tid == 0) { ssq = g_sumsq; g_sumsq = 0.f; g_ticket = 0u; }

#pragma unroll
    for (int o = 16; o > 0; o >>= 1) ipart += __shfl_down_sync(0xffffffffu, ipart, o);
    if (l == 0) s_red[w] = ipart;

    // pairwise hinge: one (i,j) pair per warp iteration, lanes cover 128 dims as float4
    const float4* cent4 = (const float4*)cent;
    float hsum = 0.f;
    for (int i = w; i < NUM_C - 1; i += 4) {
        float4 a = cent4[i * FD4 + l];
        for (int j = i + 1; j < NUM_C; j++) {
            float4 b = cent4[j * FD4 + l];
            float dx = a.x - b.x, dy = a.y - b.y, dz = a.z - b.z, dw = a.w - b.w;
            float d2 = dx * dx + dy * dy + dz * dz + dw * dw;
#pragma unroll
            for (int o = 16; o > 0; o >>= 1) d2 += __shfl_down_sync(0xffffffffu, d2, o);
            if (l == 0) {
                float wt = (i == 1 && j == 2) ? 2.0f : 1.0f;
                hsum += wt * fmaxf(2.0f - d2, 0.0f);        // MARGIN = 2
            }
        }
    }
    if (l == 0) s_hred[w] = hsum;
    __syncthreads();

    if (tid == 0) {
        float isum = s_red[0] + s_red[1] + s_red[2] + s_red[3];
        float hs   = s_hred[0] + s_hred[1] + s_hred[2] + s_hred[3];
        float intra = (ssq - isum) / (float)B;
        float inter = hs / (float)N_PAIRS;
        out[0] = intra + inter;                      // lambdas = 1
    }
}

extern "C" void kernel_launch(void* const* d_in, const int* in_sizes, int n_in,
                              void* d_out, int out_size) {
    const float* feat = (const float*)d_in[0];
    const int*   tgt  = (const int*)d_in[1];
    const int B = in_sizes[1];

    cudaFuncSetAttribute(fused_k, cudaFuncAttributeMaxDynamicSharedMemorySize, SMEM_BYTES);
    fused_k<<<GRID, BLK, SMEM_BYTES>>>(feat, tgt, B, (float*)d_out);
}

// round 3
// speedup vs baseline: 4.0519x; 4.0519x over previous
#include <cuda_runtime.h>

#define NUM_C   64
#define FD      128
#define FD4     32          // float4 per feature row
#define BLK     256
#define NWARP   8
#define GRID    592         // 4 blocks per SM
#define PER_CAP 1792        // max rows per block (ceil(1e6/592)=1690)
#define DEPTH   8           // gather pipeline depth
#define N_PAIRS 2016        // 64*63/2

__device__ float        g_sums[NUM_C * FD];
__device__ int          g_counts[NUM_C];
__device__ float        g_sumsq;
__device__ unsigned int g_ticket;

__global__ void __launch_bounds__(BLK, 4)
fused_k(const float* __restrict__ feat, const int* __restrict__ tgt, int B,
        float* __restrict__ out)
{
    __shared__ unsigned char  stgt[PER_CAP];
    __shared__ unsigned short sidx[PER_CAP];
    __shared__ int   hist[NUM_C];
    __shared__ int   pref[NUM_C];
    __shared__ int   cur[NUM_C];
    __shared__ float cent[NUM_C * FD];          // epilogue only (32KB)
    __shared__ float s_red[NWARP], s_sq[NWARP], s_hred[NWARP];
    __shared__ int   s_last;

    const int tid = threadIdx.x;
    const int w = tid >> 5, l = tid & 31;

    const int per = (B + GRID - 1) / GRID;
    const int r0  = blockIdx.x * per;
    int n = B - r0; if (n > per) n = per; if (n < 0) n = 0;

    if (tid < NUM_C) hist[tid] = 0;
    __syncthreads();

    // ---- phase A: load targets, histogram ----
    for (int i = tid; i < n; i += BLK) {
        int t = tgt[r0 + i];
        stgt[i] = (unsigned char)t;
        atomicAdd(&hist[t], 1);
    }
    __syncthreads();

    // ---- exclusive prefix over 64 counts (warp 0) ----
    if (w == 0) {
        int a = hist[l], b = hist[l + 32];
        int ia = a, ib = b;
#pragma unroll
        for (int o = 1; o < 32; o <<= 1) { int t = __shfl_up_sync(0xffffffffu, ia, o); if (l >= o) ia += t; }
#pragma unroll
        for (int o = 1; o < 32; o <<= 1) { int t = __shfl_up_sync(0xffffffffu, ib, o); if (l >= o) ib += t; }
        int totA = __shfl_sync(0xffffffffu, ia, 31);
        pref[l]      = ia - a;         cur[l]      = ia - a;
        pref[l + 32] = totA + ib - b;  cur[l + 32] = totA + ib - b;
    }
    __syncthreads();

    // ---- phase B: scatter local row ids into class-sorted order ----
    for (int i = tid; i < n; i += BLK) {
        int t = stgt[i];
        int pos = atomicAdd(&cur[t], 1);
        sidx[pos] = (unsigned short)i;
    }
    __syncthreads();

    // ---- phase C: gather-accumulate (pure register chain) ----
    const float4* f4 = (const float4*)feat;
    float sq = 0.f;
#pragma unroll 1
    for (int j = 0; j < NUM_C / NWARP; j++) {
        const int c     = w + j * NWARP;
        const int start = pref[c];
        const int cnt   = hist[c];
        float4 acc = make_float4(0.f, 0.f, 0.f, 0.f);
        float4 v[DEPTH];
#pragma unroll
        for (int k = 0; k < DEPTH; k++)
            if (k < cnt) v[k] = f4[((size_t)(r0 + sidx[start + k])) * FD4 + l];
        const int ngrp = (cnt + DEPTH - 1) / DEPTH;
        for (int g = 0; g < ngrp; g++) {
            const int base = g * DEPTH;
#pragma unroll
            for (int u = 0; u < DEPTH; u++) {
                const int k = base + u;
                if (k < cnt) {
                    float4 x = v[u];
                    const int kn = k + DEPTH;
                    if (kn < cnt) v[u] = f4[((size_t)(r0 + sidx[start + kn])) * FD4 + l];
                    acc.x += x.x; acc.y += x.y; acc.z += x.z; acc.w += x.w;
                    sq = fmaf(x.x, x.x, fmaf(x.y, x.y, fmaf(x.z, x.z, fmaf(x.w, x.w, sq))));
                }
            }
        }
        if (cnt > 0) {
            float* gs = &g_sums[c * FD + (l << 2)];
            atomicAdd(gs + 0, acc.x); atomicAdd(gs + 1, acc.y);
            atomicAdd(gs + 2, acc.z); atomicAdd(gs + 3, acc.w);
        }
    }

    // ---- block-level reductions & flush ----
#pragma unroll
    for (int o = 16; o > 0; o >>= 1) sq += __shfl_down_sync(0xffffffffu, sq, o);
    if (l == 0) s_sq[w] = sq;
    if (tid < NUM_C) atomicAdd(&g_counts[tid], hist[tid]);
    __syncthreads();
    if (tid == 0) {
        float t = 0.f;
#pragma unroll
        for (int k = 0; k < NWARP; k++) t += s_sq[k];
        atomicAdd(&g_sumsq, t);
    }

    __threadfence();
    __syncthreads();
    if (tid == 0) {
        unsigned int tk = atomicAdd(&g_ticket, 1u);
        s_last = (tk == gridDim.x - 1);
    }
    __syncthreads();
    if (!s_last) return;

    // ================= last block: epilogue =================
    __threadfence();

    float ipart = 0.f;
    for (int i = tid; i < NUM_C * FD; i += BLK) {
        const int c = i >> 7;
        float cntc = fmaxf((float)g_counts[c], 1.0f);
        float s  = g_sums[i];
        float ce = s / cntc;
        cent[i]  = ce;
        ipart   += s * ce;                 // sum_c cnt_c * ||cent_c||^2
        g_sums[i] = 0.f;                   // reset for next graph replay
    }
    float ssq = 0.f;
    if (tid == 0) { ssq = g_sumsq; g_sumsq = 0.f; g_ticket = 0u; }
    __syncthreads();                       // all reads of g_counts done
    if (tid < NUM_C) g_counts[tid] = 0;

#pragma unroll
    for (int o = 16; o > 0; o >>= 1) ipart += __shfl_down_sync(0xffffffffu, ipart, o);
    if (l == 0) s_red[w] = ipart;
    __syncthreads();

    // pairwise hinge: one (i,j) pair per warp iter, lanes cover 128 dims as float4
    const float4* c4 = (const float4*)cent;
    float hsum = 0.f;
    for (int i = w; i < NUM_C - 1; i += NWARP) {
        float4 a = c4[i * FD4 + l];
        for (int j = i + 1; j < NUM_C; j++) {
            float4 b = c4[j * FD4 + l];
            float dx = a.x - b.x, dy = a.y - b.y, dz = a.z - b.z, dw = a.w - b.w;
            float d2 = dx * dx + dy * dy + dz * dz + dw * dw;
#pragma unroll
            for (int o = 16; o > 0; o >>= 1) d2 += __shfl_down_sync(0xffffffffu, d2, o);
            if (l == 0) {
                float wt = (i == 1 && j == 2) ? 2.0f : 1.0f;
                hsum += wt * fmaxf(2.0f - d2, 0.0f);     // MARGIN = 2
            }
        }
    }
    if (l == 0) s_hred[w] = hsum;
    __syncthreads();

    if (tid == 0) {
        float isum = 0.f, hs = 0.f;
#pragma unroll
        for (int k = 0; k < NWARP; k++) { isum += s_red[k]; hs += s_hred[k]; }
        out[0] = (ssq - isum) / (float)B + hs / (float)N_PAIRS;
    }
}

extern "C" void kernel_launch(void* const* d_in, const int* in_sizes, int n_in,
                              void* d_out, int out_size) {
    const float* feat = (const float*)d_in[0];
    const int*   tgt  = (const int*)d_in[1];
    const int B = in_sizes[1];
    fused_k<<<GRID, BLK>>>(feat, tgt, B, (float*)d_out);
}

// round 4
// speedup vs baseline: 5.1229x; 1.2643x over previous
#include <cuda_runtime.h>

#define NUM_C   64
#define FD      128
#define FD4     32          // float4 per feature row
#define BLK     256
#define NWARP   8
#define GRID    592         // 4 blocks per SM
#define PER_CAP 1792        // max rows per block (ceil(1e6/592)=1690)
#define GRP     8           // rows per warp-group iteration
#define N_PAIRS 2016        // 64*63/2

__device__ float        g_sums[NUM_C * FD];
__device__ int          g_counts[NUM_C];
__device__ float        g_sumsq;
__device__ unsigned int g_ticket;

__device__ __forceinline__ void flush_acc(int c, int l, const float4& a) {
    float* gs = &g_sums[c * FD + (l << 2)];
    atomicAdd(gs + 0, a.x); atomicAdd(gs + 1, a.y);
    atomicAdd(gs + 2, a.z); atomicAdd(gs + 3, a.w);
}

__global__ void __launch_bounds__(BLK, 4)
fused_k(const float* __restrict__ feat, const int* __restrict__ tgt, int B,
        float* __restrict__ out)
{
    __shared__ unsigned short sidx[PER_CAP];     // sorted local row id
    __shared__ unsigned char  scls[PER_CAP];     // sorted class id
    __shared__ unsigned char  stgt[PER_CAP];
    __shared__ int   hist[NUM_C];
    __shared__ int   cur[NUM_C];
    __shared__ float cent[NUM_C * FD];           // epilogue only (32KB)
    __shared__ float s_red[NWARP], s_sq[NWARP], s_hred[NWARP];
    __shared__ int   s_last;

    const int tid = threadIdx.x;
    const int w = tid >> 5, l = tid & 31;

    const int per = (B + GRID - 1) / GRID;
    const int r0  = blockIdx.x * per;
    int n = B - r0; if (n > per) n = per; if (n < 0) n = 0;

    if (tid < NUM_C) hist[tid] = 0;
    __syncthreads();

    // ---- phase A: load targets, histogram ----
    for (int i = tid; i < n; i += BLK) {
        int t = tgt[r0 + i];
        stgt[i] = (unsigned char)t;
        atomicAdd(&hist[t], 1);
    }
    __syncthreads();

    // ---- exclusive prefix over 64 counts (warp 0) ----
    if (w == 0) {
        int a = hist[l], b = hist[l + 32];
        int ia = a, ib = b;
#pragma unroll
        for (int o = 1; o < 32; o <<= 1) { int t = __shfl_up_sync(0xffffffffu, ia, o); if (l >= o) ia += t; }
#pragma unroll
        for (int o = 1; o < 32; o <<= 1) { int t = __shfl_up_sync(0xffffffffu, ib, o); if (l >= o) ib += t; }
        int totA = __shfl_sync(0xffffffffu, ia, 31);
        cur[l]      = ia - a;
        cur[l + 32] = totA + ib - b;
    }
    __syncthreads();

    // ---- phase B: scatter local row ids into class-sorted order ----
    for (int i = tid; i < n; i += BLK) {
        int t = stgt[i];
        int pos = atomicAdd(&cur[t], 1);
        sidx[pos] = (unsigned short)i;
        scls[pos] = (unsigned char)t;
    }
    __syncthreads();

    // ---- phase C: contiguous-chunk gather, register accumulate ----
    const float4* f4 = (const float4*)feat;
    const int p0 = (n * w) / NWARP;
    const int p1 = (n * (w + 1)) / NWARP;

    float sq0 = 0.f, sq1 = 0.f;
    float4 acc = make_float4(0.f, 0.f, 0.f, 0.f);
    int ccur = (p0 < p1) ? (int)scls[p0] : 0;

    int p = p0;
    for (; p + GRP <= p1; p += GRP) {
        int idx[GRP], cls[GRP];
#pragma unroll
        for (int u = 0; u < GRP; u++) { idx[u] = sidx[p + u]; cls[u] = scls[p + u]; }
        float4 v[GRP];
#pragma unroll
        for (int u = 0; u < GRP; u++)
            v[u] = f4[(size_t)(r0 + idx[u]) * FD4 + l];   // unconditional, front-batched
#pragma unroll
        for (int u = 0; u < GRP; u++) {
            float4 x = v[u];
            if (cls[u] != ccur) {                          // warp-uniform, rare
                flush_acc(ccur, l, acc);
                acc = make_float4(0.f, 0.f, 0.f, 0.f);
                ccur = cls[u];
            }
            acc.x += x.x; acc.y += x.y; acc.z += x.z; acc.w += x.w;
            if (u & 1) sq1 = fmaf(x.x, x.x, fmaf(x.y, x.y, fmaf(x.z, x.z, fmaf(x.w, x.w, sq1))));
            else       sq0 = fmaf(x.x, x.x, fmaf(x.y, x.y, fmaf(x.z, x.z, fmaf(x.w, x.w, sq0))));
        }
    }
    for (; p < p1; p++) {
        int i2 = sidx[p], c = scls[p];
        float4 x = f4[(size_t)(r0 + i2) * FD4 + l];
        if (c != ccur) {
            flush_acc(ccur, l, acc);
            acc = make_float4(0.f, 0.f, 0.f, 0.f);
            ccur = c;
        }
        acc.x += x.x; acc.y += x.y; acc.z += x.z; acc.w += x.w;
        sq0 = fmaf(x.x, x.x, fmaf(x.y, x.y, fmaf(x.z, x.z, fmaf(x.w, x.w, sq0))));
    }
    if (p1 > p0) flush_acc(ccur, l, acc);

    // ---- block-level reductions & flush ----
    float sq = sq0 + sq1;
#pragma unroll
    for (int o = 16; o > 0; o >>= 1) sq += __shfl_down_sync(0xffffffffu, sq, o);
    if (l == 0) s_sq[w] = sq;
    if (tid < NUM_C) atomicAdd(&g_counts[tid], hist[tid]);
    __syncthreads();
    if (tid == 0) {
        float t = 0.f;
#pragma unroll
        for (int k = 0; k < NWARP; k++) t += s_sq[k];
        atomicAdd(&g_sumsq, t);
    }

    __threadfence();
    __syncthreads();
    if (tid == 0) {
        unsigned int tk = atomicAdd(&g_ticket, 1u);
        s_last = (tk == gridDim.x - 1);
    }
    __syncthreads();
    if (!s_last) return;

    // ================= last block: epilogue =================
    __threadfence();

    float ipart = 0.f;
    for (int i = tid; i < NUM_C * FD; i += BLK) {
        const int c = i >> 7;
        float cntc = fmaxf((float)g_counts[c], 1.0f);
        float s  = g_sums[i];
        float ce = s / cntc;
        cent[i]  = ce;
        ipart   += s * ce;                 // sum_c cnt_c * ||cent_c||^2
        g_sums[i] = 0.f;                   // reset for next graph replay
    }
    float ssq = 0.f;
    if (tid == 0) { ssq = g_sumsq; g_sumsq = 0.f; g_ticket = 0u; }
    __syncthreads();                       // all reads of g_counts done
    if (tid < NUM_C) g_counts[tid] = 0;

#pragma unroll
    for (int o = 16; o > 0; o >>= 1) ipart += __shfl_down_sync(0xffffffffu, ipart, o);
    if (l == 0) s_red[w] = ipart;
    __syncthreads();

    // pairwise hinge: one (i,j) pair per warp iter, lanes cover 128 dims as float4
    const float4* c4 = (const float4*)cent;
    float hsum = 0.f;
    for (int i = w; i < NUM_C - 1; i += NWARP) {
        float4 a = c4[i * FD4 + l];
        for (int j = i + 1; j < NUM_C; j++) {
            float4 b = c4[j * FD4 + l];
            float dx = a.x - b.x, dy = a.y - b.y, dz = a.z - b.z, dw = a.w - b.w;
            float d2 = dx * dx + dy * dy + dz * dz + dw * dw;
#pragma unroll
            for (int o = 16; o > 0; o >>= 1) d2 += __shfl_down_sync(0xffffffffu, d2, o);
            if (l == 0) {
                float wt = (i == 1 && j == 2) ? 2.0f : 1.0f;
                hsum += wt * fmaxf(2.0f - d2, 0.0f);     // MARGIN = 2
            }
        }
    }
    if (l == 0) s_hred[w] = hsum;
    __syncthreads();

    if (tid == 0) {
        float isum = 0.f, hs = 0.f;
#pragma unroll
        for (int k = 0; k < NWARP; k++) { isum += s_red[k]; hs += s_hred[k]; }
        out[0] = (ssq - isum) / (float)B + hs / (float)N_PAIRS;
    }
}

extern "C" void kernel_launch(void* const* d_in, const int* in_sizes, int n_in,
                              void* d_out, int out_size) {
    const float* feat = (const float*)d_in[0];
    const int*   tgt  = (const int*)d_in[1];
    const int B = in_sizes[1];
    fused_k<<<GRID, BLK>>>(feat, tgt, B, (float*)d_out);
}

// round 5
// speedup vs baseline: 5.2691x; 1.0285x over previous
#include <cuda_runtime.h>

#define NUM_C   64
#define FD      128
#define FD4     32          // float4 per feature row
#define BLK     256
#define NWARP   8
#define GRID    444         // 3 blocks per SM (148 SMs)
#define PER_CAP 2304        // max rows per block (ceil(1e6/444)=2253)
#define GRP     8           // rows per warp-group iteration
#define N_PAIRS 2016        // 64*63/2

__device__ float        g_sums[NUM_C * FD];
__device__ int          g_counts[NUM_C];
__device__ float        g_sumsq;
__device__ unsigned int g_ticket;

__device__ __forceinline__ void flush_acc(int c, int l, const float4& a) {
    float* gs = &g_sums[c * FD + (l << 2)];
    atomicAdd(gs + 0, a.x); atomicAdd(gs + 1, a.y);
    atomicAdd(gs + 2, a.z); atomicAdd(gs + 3, a.w);
}

__global__ void __launch_bounds__(BLK, 3)
fused_k(const float* __restrict__ feat, const int* __restrict__ tgt, int B,
        float* __restrict__ out)
{
    __shared__ unsigned int  scomb[PER_CAP];     // sorted: rowid | (class<<16)
    __shared__ unsigned char stgt[PER_CAP];
    __shared__ int   hist[NUM_C];
    __shared__ int   cur[NUM_C];
    __shared__ float cent[NUM_C * FD];           // epilogue only (32KB)
    __shared__ float s_red[NWARP], s_sq[NWARP], s_hred[NWARP];
    __shared__ int   s_last;

    const int tid = threadIdx.x;
    const int w = tid >> 5, l = tid & 31;

    const int per = (B + GRID - 1) / GRID;
    const int r0  = blockIdx.x * per;
    int n = B - r0; if (n > per) n = per; if (n < 0) n = 0;

    if (tid < NUM_C) hist[tid] = 0;
    __syncthreads();

    // ---- phase A: load targets, histogram ----
    for (int i = tid; i < n; i += BLK) {
        int t = tgt[r0 + i];
        stgt[i] = (unsigned char)t;
        atomicAdd(&hist[t], 1);
    }
    __syncthreads();

    // ---- exclusive prefix over 64 counts (warp 0) ----
    if (w == 0) {
        int a = hist[l], b = hist[l + 32];
        int ia = a, ib = b;
#pragma unroll
        for (int o = 1; o < 32; o <<= 1) { int t = __shfl_up_sync(0xffffffffu, ia, o); if (l >= o) ia += t; }
#pragma unroll
        for (int o = 1; o < 32; o <<= 1) { int t = __shfl_up_sync(0xffffffffu, ib, o); if (l >= o) ib += t; }
        int totA = __shfl_sync(0xffffffffu, ia, 31);
        cur[l]      = ia - a;
        cur[l + 32] = totA + ib - b;
    }
    __syncthreads();

    // ---- phase B: scatter (rowid | class<<16) into class-sorted order ----
    for (int i = tid; i < n; i += BLK) {
        int t = stgt[i];
        int pos = atomicAdd(&cur[t], 1);
        scomb[pos] = (unsigned int)i | ((unsigned int)t << 16);
    }
    __syncthreads();

    // ---- phase C: contiguous-chunk gather, register accumulate ----
    const float4* f4 = (const float4*)feat;
    const int p0 = (n * w) / NWARP;
    const int p1 = (n * (w + 1)) / NWARP;

    float sq0 = 0.f, sq1 = 0.f;
    float4 acc = make_float4(0.f, 0.f, 0.f, 0.f);
    int ccur = (p0 < p1) ? (int)(scomb[p0] >> 16) : 0;

    int p = p0;
    for (; p + GRP <= p1; p += GRP) {
        unsigned int cb[GRP];
#pragma unroll
        for (int u = 0; u < GRP; u++) cb[u] = scomb[p + u];
        float4 v[GRP];
#pragma unroll
        for (int u = 0; u < GRP; u++)
            v[u] = f4[(size_t)(r0 + (cb[u] & 0xffffu)) * FD4 + l];  // unconditional batch
#pragma unroll
        for (int u = 0; u < GRP; u++) {
            float4 x = v[u];
            int c = (int)(cb[u] >> 16);
            if (c != ccur) {                          // warp-uniform, rare
                flush_acc(ccur, l, acc);
                acc = make_float4(0.f, 0.f, 0.f, 0.f);
                ccur = c;
            }
            acc.x += x.x; acc.y += x.y; acc.z += x.z; acc.w += x.w;
            if (u & 1) sq1 = fmaf(x.x, x.x, fmaf(x.y, x.y, fmaf(x.z, x.z, fmaf(x.w, x.w, sq1))));
            else       sq0 = fmaf(x.x, x.x, fmaf(x.y, x.y, fmaf(x.z, x.z, fmaf(x.w, x.w, sq0))));
        }
    }
    for (; p < p1; p++) {
        unsigned int cb = scomb[p];
        int c = (int)(cb >> 16);
        float4 x = f4[(size_t)(r0 + (cb & 0xffffu)) * FD4 + l];
        if (c != ccur) {
            flush_acc(ccur, l, acc);
            acc = make_float4(0.f, 0.f, 0.f, 0.f);
            ccur = c;
        }
        acc.x += x.x; acc.y += x.y; acc.z += x.z; acc.w += x.w;
        sq0 = fmaf(x.x, x.x, fmaf(x.y, x.y, fmaf(x.z, x.z, fmaf(x.w, x.w, sq0))));
    }
    if (p1 > p0) flush_acc(ccur, l, acc);

    // ---- block-level reductions & flush ----
    float sq = sq0 + sq1;
#pragma unroll
    for (int o = 16; o > 0; o >>= 1) sq += __shfl_down_sync(0xffffffffu, sq, o);
    if (l == 0) s_sq[w] = sq;
    if (tid < NUM_C) atomicAdd(&g_counts[tid], hist[tid]);
    __syncthreads();
    if (tid == 0) {
        float t = 0.f;
#pragma unroll
        for (int k = 0; k < NWARP; k++) t += s_sq[k];
        atomicAdd(&g_sumsq, t);
    }

    __threadfence();
    __syncthreads();
    if (tid == 0) {
        unsigned int tk = atomicAdd(&g_ticket, 1u);
        s_last = (tk == gridDim.x - 1);
    }
    __syncthreads();
    if (!s_last) return;

    // ================= last block: epilogue =================
    __threadfence();

    float ipart = 0.f;
    for (int i = tid; i < NUM_C * FD; i += BLK) {
        const int c = i >> 7;
        float cntc = fmaxf((float)g_counts[c], 1.0f);
        float s  = g_sums[i];
        float ce = s / cntc;
        cent[i]  = ce;
        ipart   += s * ce;                 // sum_c cnt_c * ||cent_c||^2
        g_sums[i] = 0.f;                   // reset for next graph replay
    }
    float ssq = 0.f;
    if (tid == 0) { ssq = g_sumsq; g_sumsq = 0.f; g_ticket = 0u; }
    __syncthreads();                       // all reads of g_counts done
    if (tid < NUM_C) g_counts[tid] = 0;

#pragma unroll
    for (int o = 16; o > 0; o >>= 1) ipart += __shfl_down_sync(0xffffffffu, ipart, o);
    if (l == 0) s_red[w] = ipart;
    __syncthreads();

    // pairwise hinge: one (i,j) pair per warp iter, lanes cover 128 dims as float4
    const float4* c4 = (const float4*)cent;
    float hsum = 0.f;
    for (int i = w; i < NUM_C - 1; i += NWARP) {
        float4 a = c4[i * FD4 + l];
        for (int j = i + 1; j < NUM_C; j++) {
            float4 b = c4[j * FD4 + l];
            float dx = a.x - b.x, dy = a.y - b.y, dz = a.z - b.z, dw = a.w - b.w;
            float d2 = dx * dx + dy * dy + dz * dz + dw * dw;
#pragma unroll
            for (int o = 16; o > 0; o >>= 1) d2 += __shfl_down_sync(0xffffffffu, d2, o);
            if (l == 0) {
                float wt = (i == 1 && j == 2) ? 2.0f : 1.0f;
                hsum += wt * fmaxf(2.0f - d2, 0.0f);     // MARGIN = 2
            }
        }
    }
    if (l == 0) s_hred[w] = hsum;
    __syncthreads();

    if (tid == 0) {
        float isum = 0.f, hs = 0.f;
#pragma unroll
        for (int k = 0; k < NWARP; k++) { isum += s_red[k]; hs += s_hred[k]; }
        out[0] = (ssq - isum) / (float)B + hs / (float)N_PAIRS;
    }
}

extern "C" void kernel_launch(void* const* d_in, const int* in_sizes, int n_in,
                              void* d_out, int out_size) {
    const float* feat = (const float*)d_in[0];
    const int*   tgt  = (const int*)d_in[1];
    const int B = in_sizes[1];
    fused_k<<<GRID, BLK>>>(feat, tgt, B, (float*)d_out);
}

// round 6
// speedup vs baseline: 5.5349x; 1.0505x over previous
#include <cuda_runtime.h>

#define NUM_C   64
#define FD      128
#define FD4     32          // float4 per feature row
#define BLK     256
#define NWARP   8
#define GRID    444         // 3 blocks per SM (148 SMs)
#define PER_CAP 2304        // max rows per block (ceil(1e6/444)=2253)
#define GRP     4           // rows per pipelined group
#define N_PAIRS 2016        // 64*63/2

__device__ float        g_sums[NUM_C * FD];
__device__ int          g_counts[NUM_C];
__device__ float        g_sumsq;
__device__ unsigned int g_ticket;

__device__ __forceinline__ void flush_acc(int c, int l, const float4& a) {
    float* gs = &g_sums[c * FD + (l << 2)];
    atomicAdd(gs + 0, a.x); atomicAdd(gs + 1, a.y);
    atomicAdd(gs + 2, a.z); atomicAdd(gs + 3, a.w);
}

__device__ __forceinline__ void load_grp(const float4* __restrict__ fl, int r0,
                                         const unsigned int* scomb, int p,
                                         unsigned int* cb, float4* v) {
#pragma unroll
    for (int u = 0; u < GRP; u++) cb[u] = scomb[p + u];      // uniform (broadcast) LDS
#pragma unroll
    for (int u = 0; u < GRP; u++)
        v[u] = fl[(size_t)(r0 + (cb[u] & 0xffffu)) * FD4];   // unconditional LDG.128 batch
}

__device__ __forceinline__ void comp_grp(const unsigned int* cb, const float4* v, int l,
                                         int& ccur, float4& acc, float& sq0, float& sq1) {
#pragma unroll
    for (int u = 0; u < GRP; u++) {
        float4 x = v[u];
        int c = (int)(cb[u] >> 16);
        if (c != ccur) {                                     // warp-uniform, rare
            flush_acc(ccur, l, acc);
            acc = make_float4(0.f, 0.f, 0.f, 0.f);
            ccur = c;
        }
        acc.x += x.x; acc.y += x.y; acc.z += x.z; acc.w += x.w;
        if (u & 1) sq1 = fmaf(x.x, x.x, fmaf(x.y, x.y, fmaf(x.z, x.z, fmaf(x.w, x.w, sq1))));
        else       sq0 = fmaf(x.x, x.x, fmaf(x.y, x.y, fmaf(x.z, x.z, fmaf(x.w, x.w, sq0))));
    }
}

__global__ void __launch_bounds__(BLK, 3)
fused_k(const float* __restrict__ feat, const int* __restrict__ tgt, int B,
        float* __restrict__ out)
{
    __shared__ unsigned int  scomb[PER_CAP];     // sorted: rowid | (class<<16)
    __shared__ unsigned char stgt[PER_CAP];
    __shared__ int   hist[NUM_C];
    __shared__ int   cur[NUM_C];
    __shared__ float cent[NUM_C * FD];           // epilogue only (32KB)
    __shared__ float s_red[NWARP], s_sq[NWARP], s_hred[NWARP];
    __shared__ int   s_last;

    const int tid = threadIdx.x;
    const int w = tid >> 5, l = tid & 31;

    const int per = (B + GRID - 1) / GRID;
    const int r0  = blockIdx.x * per;
    int n = B - r0; if (n > per) n = per; if (n < 0) n = 0;

    if (tid < NUM_C) hist[tid] = 0;
    __syncthreads();

    // ---- phase A: load targets, histogram ----
    for (int i = tid; i < n; i += BLK) {
        int t = tgt[r0 + i];
        stgt[i] = (unsigned char)t;
        atomicAdd(&hist[t], 1);
    }
    __syncthreads();

    // ---- exclusive prefix over 64 counts (warp 0) ----
    if (w == 0) {
        int a = hist[l], b = hist[l + 32];
        int ia = a, ib = b;
#pragma unroll
        for (int o = 1; o < 32; o <<= 1) { int t = __shfl_up_sync(0xffffffffu, ia, o); if (l >= o) ia += t; }
#pragma unroll
        for (int o = 1; o < 32; o <<= 1) { int t = __shfl_up_sync(0xffffffffu, ib, o); if (l >= o) ib += t; }
        int totA = __shfl_sync(0xffffffffu, ia, 31);
        cur[l]      = ia - a;
        cur[l + 32] = totA + ib - b;
    }
    __syncthreads();

    // ---- phase B: scatter (rowid | class<<16) into class-sorted order ----
    for (int i = tid; i < n; i += BLK) {
        int t = stgt[i];
        int pos = atomicAdd(&cur[t], 1);
        scomb[pos] = (unsigned int)i | ((unsigned int)t << 16);
    }
    __syncthreads();

    // ---- phase C: double-buffered gather, register accumulate ----
    const float4* fl = (const float4*)feat + l;   // lane offset pre-added
    const int p0 = (n * w) / NWARP;
    const int p1 = (n * (w + 1)) / NWARP;

    float sq0 = 0.f, sq1 = 0.f;
    float4 acc = make_float4(0.f, 0.f, 0.f, 0.f);
    int ccur = (p0 < p1) ? (int)(scomb[p0] >> 16) : 0;

    const int full = (p1 - p0) >> 2;              // number of GRP-row groups
    int p = p0, g = 0;

    unsigned int ca[GRP], cbf[GRP];
    float4 va[GRP], vb[GRP];

    if (full > 0) load_grp(fl, r0, scomb, p, ca, va);        // preload group 0
    while (g + 2 <= full) {
        load_grp(fl, r0, scomb, p + GRP, cbf, vb);           // prefetch g+1
        comp_grp(ca, va, l, ccur, acc, sq0, sq1);            // compute g
        if (g + 2 < full) load_grp(fl, r0, scomb, p + 2 * GRP, ca, va);  // prefetch g+2
        comp_grp(cbf, vb, l, ccur, acc, sq0, sq1);           // compute g+1
        p += 2 * GRP; g += 2;
    }
    if (g < full) {                                          // odd leftover (preloaded in va)
        comp_grp(ca, va, l, ccur, acc, sq0, sq1);
        p += GRP; g++;
    }
    for (; p < p1; p++) {                                    // scalar tail (<GRP rows)
        unsigned int cb = scomb[p];
        int c = (int)(cb >> 16);
        float4 x = fl[(size_t)(r0 + (cb & 0xffffu)) * FD4];
        if (c != ccur) {
            flush_acc(ccur, l, acc);
            acc = make_float4(0.f, 0.f, 0.f, 0.f);
            ccur = c;
        }
        acc.x += x.x; acc.y += x.y; acc.z += x.z; acc.w += x.w;
        sq0 = fmaf(x.x, x.x, fmaf(x.y, x.y, fmaf(x.z, x.z, fmaf(x.w, x.w, sq0))));
    }
    if (p1 > p0) flush_acc(ccur, l, acc);

    // ---- block-level reductions & flush ----
    float sq = sq0 + sq1;
#pragma unroll
    for (int o = 16; o > 0; o >>= 1) sq += __shfl_down_sync(0xffffffffu, sq, o);
    if (l == 0) s_sq[w] = sq;
    if (tid < NUM_C) atomicAdd(&g_counts[tid], hist[tid]);
    __syncthreads();
    if (tid == 0) {
        float t = 0.f;
#pragma unroll
        for (int k = 0; k < NWARP; k++) t += s_sq[k];
        atomicAdd(&g_sumsq, t);
    }

    __threadfence();
    __syncthreads();
    if (tid == 0) {
        unsigned int tk = atomicAdd(&g_ticket, 1u);
        s_last = (tk == gridDim.x - 1);
    }
    __syncthreads();
    if (!s_last) return;

    // ================= last block: epilogue =================
    __threadfence();

    float ipart = 0.f;
    for (int i = tid; i < NUM_C * FD; i += BLK) {
        const int c = i >> 7;
        float cntc = fmaxf((float)g_counts[c], 1.0f);
        float s  = g_sums[i];
        float ce = s / cntc;
        cent[i]  = ce;
        ipart   += s * ce;                 // sum_c cnt_c * ||cent_c||^2
        g_sums[i] = 0.f;                   // reset for next graph replay
    }
    float ssq = 0.f;
    if (tid == 0) { ssq = g_sumsq; g_sumsq = 0.f; g_ticket = 0u; }
    __syncthreads();                       // all reads of g_counts done
    if (tid < NUM_C) g_counts[tid] = 0;

#pragma unroll
    for (int o = 16; o > 0; o >>= 1) ipart += __shfl_down_sync(0xffffffffu, ipart, o);
    if (l == 0) s_red[w] = ipart;
    __syncthreads();

    // pairwise hinge: one (i,j) pair per warp iter, lanes cover 128 dims as float4
    const float4* c4 = (const float4*)cent;
    float hsum = 0.f;
    for (int i = w; i < NUM_C - 1; i += NWARP) {
        float4 a = c4[i * FD4 + l];
        for (int j = i + 1; j < NUM_C; j++) {
            float4 b = c4[j * FD4 + l];
            float dx = a.x - b.x, dy = a.y - b.y, dz = a.z - b.z, dw = a.w - b.w;
            float d2 = dx * dx + dy * dy + dz * dz + dw * dw;
#pragma unroll
            for (int o = 16; o > 0; o >>= 1) d2 += __shfl_down_sync(0xffffffffu, d2, o);
            if (l == 0) {
                float wt = (i == 1 && j == 2) ? 2.0f : 1.0f;
                hsum += wt * fmaxf(2.0f - d2, 0.0f);     // MARGIN = 2
            }
        }
    }
    if (l == 0) s_hred[w] = hsum;
    __syncthreads();

    if (tid == 0) {
        float isum = 0.f, hs = 0.f;
#pragma unroll
        for (int k = 0; k < NWARP; k++) { isum += s_red[k]; hs += s_hred[k]; }
        out[0] = (ssq - isum) / (float)B + hs / (float)N_PAIRS;
    }
}

extern "C" void kernel_launch(void* const* d_in, const int* in_sizes, int n_in,
                              void* d_out, int out_size) {
    const float* feat = (const float*)d_in[0];
    const int*   tgt  = (const int*)d_in[1];
    const int B = in_sizes[1];
    fused_k<<<GRID, BLK>>>(feat, tgt, B, (float*)d_out);
}